// round 16
// baseline (speedup 1.0000x reference)
#include <cuda_runtime.h>

// Direction table: E = 2,000,000 edges; float4 for 16B-aligned gathers.
// 2.1M * 16B = 33.6 MB static __device__ array; fully L2-resident (126 MB L2).
#define MAX_E 2100000

static __device__ float4   g_dir[MAX_E];
static __device__ int      g_idx_is64;
static __device__ unsigned g_arrive;   // zero-initialized; self-resetting
static __device__ unsigned g_depart;

// ---------------------------------------------------------------------------
// Cache-policy load/store helpers
// ---------------------------------------------------------------------------
__device__ __forceinline__ unsigned long long evict_last_policy()
{
    unsigned long long pol;
    asm volatile("createpolicy.fractional.L2::evict_last.b64 %0, 1.0;" : "=l"(pol));
    return pol;
}

__device__ __forceinline__ float4 ldg_table(const float4* p, unsigned long long pol)
{
    float4 v;
    asm volatile("ld.global.nc.L2::cache_hint.v4.f32 {%0,%1,%2,%3}, [%4], %5;"
                 : "=f"(v.x), "=f"(v.y), "=f"(v.z), "=f"(v.w)
                 : "l"(p), "l"(pol));
    return v;
}

__device__ __forceinline__ longlong2 ldcs_ll2(const longlong2* p)
{
    longlong2 v;
    asm volatile("ld.global.cs.v2.s64 {%0,%1}, [%2];"
                 : "=l"(v.x), "=l"(v.y) : "l"(p));
    return v;
}

__device__ __forceinline__ int4 ldcs_i4(const int4* p)
{
    int4 v;
    asm volatile("ld.global.cs.v4.s32 {%0,%1,%2,%3}, [%4];"
                 : "=r"(v.x), "=r"(v.y), "=r"(v.z), "=r"(v.w) : "l"(p));
    return v;
}

__device__ __forceinline__ void stcs_f4(float4* p, float4 v)
{
    asm volatile("st.global.cs.v4.f32 [%0], {%1,%2,%3,%4};"
                 :: "l"(p), "f"(v.x), "f"(v.y), "f"(v.z), "f"(v.w) : "memory");
}

// ---------------------------------------------------------------------------
// Fused persistent kernel: phase 1 builds the dir table (grid-stride,
// scalar coalesced loads -- fastest measured variant), then a device-wide
// spin barrier (all blocks co-resident by construction), then phase 2
// processes angle pairs grid-stride, 4 pairs/step with two batches of 4
// gathers. Barrier counters self-reset for graph replays.
// ---------------------------------------------------------------------------
__global__ void __launch_bounds__(256, 8) fused_kernel(
        const float* __restrict__ dist,
        const float* __restrict__ vec,
        const void*  __restrict__ src_v,
        const void*  __restrict__ dst_v,
        float*       __restrict__ out,
        int E, int A)
{
    const int tid   = threadIdx.x;
    const int gsize = gridDim.x * blockDim.x;
    const int gt    = blockIdx.x * blockDim.x + tid;

    // ---- index dtype detection (block 0 / warp 0) ----
    // int64 little-endian with values < 2M -> odd 32-bit words are all zero.
    if (blockIdx.x == 0 && tid < 32) {
        const unsigned int* words = (const unsigned int*)src_v;
        int n = A < 256 ? A : 256;
        int zeros = 0;
        for (int j = tid; j < n; j += 32)
            zeros += (words[2 * j + 1] == 0u) ? 1 : 0;
        #pragma unroll
        for (int off = 16; off > 0; off >>= 1)
            zeros += __shfl_down_sync(0xFFFFFFFFu, zeros, off);
        if (tid == 0)
            g_idx_is64 = (zeros >= (n * 3) / 4) ? 1 : 0;  // published by barrier release
    }

    // ---- phase 1: dir[i] = vec[i] / max(dist[i], 1e-5) ----
    for (int i = gt; i < E; i += gsize) {
        float inv = 1.0f / fmaxf(__ldcs(dist + i), 1e-5f);
        float x = __ldcs(vec + 3 * i + 0) * inv;
        float y = __ldcs(vec + 3 * i + 1) * inv;
        float z = __ldcs(vec + 3 * i + 2) * inv;
        g_dir[i] = make_float4(x, y, z, 0.0f);
    }

    // ---- device-wide barrier (release-arrive / acquire-poll) ----
    __syncthreads();
    if (tid == 0) {
        unsigned long long addr = (unsigned long long)&g_arrive;
        asm volatile("red.release.gpu.global.add.u32 [%0], 1;" :: "l"(addr) : "memory");
        unsigned v;
        do {
            asm volatile("ld.acquire.gpu.global.u32 %0, [%1];" : "=r"(v) : "l"(addr) : "memory");
        } while (v < gridDim.x);
    }
    __syncthreads();

    // ---- phase 2: angle pairs ----
    unsigned long long pol = evict_last_policy();
    const int is64 = g_idx_is64;
    const int A4 = A & ~3;
    const int stride = gsize * 4;

    for (int i0 = gt * 4; i0 < A4; i0 += stride) {
        int s[4], d[4];
        if (is64) {
            const long long* sp = (const long long*)src_v + i0;
            const long long* dp = (const long long*)dst_v + i0;
            longlong2 sa = ldcs_ll2((const longlong2*)sp);
            longlong2 sb = ldcs_ll2((const longlong2*)(sp + 2));
            longlong2 da = ldcs_ll2((const longlong2*)dp);
            longlong2 db = ldcs_ll2((const longlong2*)(dp + 2));
            s[0] = (int)sa.x; s[1] = (int)sa.y; s[2] = (int)sb.x; s[3] = (int)sb.y;
            d[0] = (int)da.x; d[1] = (int)da.y; d[2] = (int)db.x; d[3] = (int)db.y;
        } else {
            int4 sa = ldcs_i4((const int4*)((const int*)src_v + i0));
            int4 da = ldcs_i4((const int4*)((const int*)dst_v + i0));
            s[0] = sa.x; s[1] = sa.y; s[2] = sa.z; s[3] = sa.w;
            d[0] = da.x; d[1] = da.y; d[2] = da.z; d[3] = da.w;
        }

        // Batch 1: 4 gathers in flight, consume, release registers.
        float4 a0 = ldg_table(&g_dir[s[0]], pol);
        float4 b0 = ldg_table(&g_dir[d[0]], pol);
        float4 a1 = ldg_table(&g_dir[s[1]], pol);
        float4 b1 = ldg_table(&g_dir[d[1]], pol);
        float c0 = a0.x * b0.x + a0.y * b0.y + a0.z * b0.z;
        float c1 = a1.x * b1.x + a1.y * b1.y + a1.z * b1.z;
        float r0 = acosf(0.95f * c0);
        float r1 = acosf(0.95f * c1);

        // Batch 2.
        float4 a2 = ldg_table(&g_dir[s[2]], pol);
        float4 b2 = ldg_table(&g_dir[d[2]], pol);
        float4 a3 = ldg_table(&g_dir[s[3]], pol);
        float4 b3 = ldg_table(&g_dir[d[3]], pol);
        float c2 = a2.x * b2.x + a2.y * b2.y + a2.z * b2.z;
        float c3 = a3.x * b3.x + a3.y * b3.y + a3.z * b3.z;

        float4 r = make_float4(r0, r1, acosf(0.95f * c2), acosf(0.95f * c3));
        stcs_f4((float4*)(out + i0), r);
    }

    // Tail pairs (A % 4) on block 0.
    if (blockIdx.x == 0) {
        for (int i = A4 + tid; i < A; i += blockDim.x) {
            int si, di;
            if (is64) {
                si = (int)((const long long*)src_v)[i];
                di = (int)((const long long*)dst_v)[i];
            } else {
                si = ((const int*)src_v)[i];
                di = ((const int*)dst_v)[i];
            }
            float4 a = ldg_table(&g_dir[si], pol);
            float4 b = ldg_table(&g_dir[di], pol);
            float c = a.x * b.x + a.y * b.y + a.z * b.z;
            out[i] = acosf(0.95f * c);
        }
    }

    // ---- self-resetting counters for deterministic graph replay ----
    __syncthreads();
    if (tid == 0) {
        unsigned dpt = atomicAdd(&g_depart, 1u);
        if (dpt == gridDim.x - 1u) {   // last block out resets both
            g_arrive = 0u;
            g_depart = 0u;
            __threadfence();
        }
    }
}

// ---------------------------------------------------------------------------
// Launch
// inputs (metadata order): distances [E] f32, vec [E,3] f32,
//                          angle_src [A] i64/i32, angle_dst [A] i64/i32
// output: angles [A] f32
// ---------------------------------------------------------------------------
extern "C" void kernel_launch(void* const* d_in, const int* in_sizes, int n_in,
                              void* d_out, int out_size)
{
    const float* dist = (const float*)d_in[0];
    const float* vec  = (const float*)d_in[1];
    const void*  src  = d_in[2];
    const void*  dst  = d_in[3];
    float*       out  = (float*)d_out;

    int E = in_sizes[0];
    int A = in_sizes[2];
    if (E > MAX_E) E = MAX_E;

    const int T = 256;

    // Guaranteed-resident grid for the spin barrier (deadlock-proof).
    static int nblocks = 0;
    if (nblocks == 0) {
        int per_sm = 0, sms = 0;
        cudaOccupancyMaxActiveBlocksPerMultiprocessor(&per_sm, fused_kernel, T, 0);
        cudaDeviceGetAttribute(&sms, cudaDevAttrMultiProcessorCount, 0);
        if (per_sm < 1) per_sm = 1;
        if (sms < 1) sms = 148;
        nblocks = per_sm * sms;
    }

    fused_kernel<<<nblocks, T>>>(dist, vec, src, dst, out, E, A);
}

// round 17
// speedup vs baseline: 1.0293x; 1.0293x over previous
#include <cuda_runtime.h>

// Direction table: E = 2,000,000 edges; float4 for 16B-aligned gathers.
// 2.1M * 16B = 33.6 MB static __device__ array; fully L2-resident (126 MB L2).
#define MAX_E 2100000

static __device__ float4 g_dir[MAX_E];
static __device__ int    g_idx_is64;

// ---------------------------------------------------------------------------
// Cache-policy load/store helpers
// ---------------------------------------------------------------------------
__device__ __forceinline__ unsigned long long evict_last_policy()
{
    unsigned long long pol;
    asm volatile("createpolicy.fractional.L2::evict_last.b64 %0, 1.0;" : "=l"(pol));
    return pol;
}

__device__ __forceinline__ float4 ldg_table(const float4* p, unsigned long long pol)
{
    float4 v;
    asm volatile("ld.global.nc.L2::cache_hint.v4.f32 {%0,%1,%2,%3}, [%4], %5;"
                 : "=f"(v.x), "=f"(v.y), "=f"(v.z), "=f"(v.w)
                 : "l"(p), "l"(pol));
    return v;
}

__device__ __forceinline__ void stg_table(float4* p, float4 v, unsigned long long pol)
{
    asm volatile("st.global.L2::cache_hint.v4.f32 [%0], {%1,%2,%3,%4}, %5;"
                 :: "l"(p), "f"(v.x), "f"(v.y), "f"(v.z), "f"(v.w), "l"(pol)
                 : "memory");
}

__device__ __forceinline__ longlong2 ldcs_ll2(const longlong2* p)
{
    longlong2 v;
    asm volatile("ld.global.cs.v2.s64 {%0,%1}, [%2];"
                 : "=l"(v.x), "=l"(v.y) : "l"(p));
    return v;
}

__device__ __forceinline__ int4 ldcs_i4(const int4* p)
{
    int4 v;
    asm volatile("ld.global.cs.v4.s32 {%0,%1,%2,%3}, [%4];"
                 : "=r"(v.x), "=r"(v.y), "=r"(v.z), "=r"(v.w) : "l"(p));
    return v;
}

__device__ __forceinline__ void stcs_f4(float4* p, float4 v)
{
    asm volatile("st.global.cs.v4.f32 [%0], {%1,%2,%3,%4};"
                 :: "l"(p), "f"(v.x), "f"(v.y), "f"(v.z), "f"(v.w) : "memory");
}

__device__ __forceinline__ void pdl_launch_dependents()
{
    asm volatile("griddepcontrol.launch_dependents;");
}

__device__ __forceinline__ void pdl_wait()
{
    asm volatile("griddepcontrol.wait;");
}

// ---------------------------------------------------------------------------
// Pass 1: dir[i] = vec[i] / max(dist[i], 1e-5).
// Scalar 1-edge/thread (fastest variant measured: consecutive threads read
// consecutive floats -> fully coalesced). Table stores carry an evict-last
// L2 hint so the table keeps residency priority over the index streams that
// start flowing during the PDL overlap window.
// Block 0 / warp 0 detects int64-vs-int32 indices; all blocks then trigger
// PDL so the angle kernel overlaps its launch + index prologue.
// ---------------------------------------------------------------------------
__global__ void dir_kernel(const float* __restrict__ dist,
                           const float* __restrict__ vec,
                           const unsigned int* __restrict__ idx_words,
                           int n_pairs,
                           int E)
{
    if (blockIdx.x == 0 && threadIdx.x < 32) {
        int n = n_pairs < 256 ? n_pairs : 256;
        int lane = threadIdx.x;
        int zeros = 0;
        for (int j = lane; j < n; j += 32)
            zeros += (idx_words[2 * j + 1] == 0u) ? 1 : 0;
        #pragma unroll
        for (int off = 16; off > 0; off >>= 1)
            zeros += __shfl_down_sync(0xFFFFFFFFu, zeros, off);
        if (lane == 0) {
            g_idx_is64 = (zeros >= (n * 3) / 4) ? 1 : 0;
            __threadfence();
        }
    }
    __syncthreads();          // flag write ordered before trigger
    pdl_launch_dependents();

    int i = blockIdx.x * blockDim.x + threadIdx.x;
    if (i >= E) return;
    unsigned long long pol = evict_last_policy();
    float inv = 1.0f / fmaxf(dist[i], 1e-5f);
    float x = vec[3 * i + 0] * inv;
    float y = vec[3 * i + 1] * inv;
    float z = vec[3 * i + 2] * inv;
    stg_table(&g_dir[i], make_float4(x, y, z, 0.0f), pol);
}

// ---------------------------------------------------------------------------
// Pass 2: 4 angle pairs per thread, gathers in two batches of 4 to keep the
// live register set <= 32 regs (launch_bounds(256,8) -> high occupancy).
// Streamed index loads (evict-first), evict-last table gathers, streamed
// vector output stores. PDL: index loads overlap dir_kernel's tail;
// griddepcontrol.wait gates the table gathers on dir_kernel completion.
// ---------------------------------------------------------------------------
__global__ void __launch_bounds__(256, 8) angle_kernel(
        const void* __restrict__ src_v,
        const void* __restrict__ dst_v,
        float* __restrict__ out,
        int A)
{
    int t  = blockIdx.x * blockDim.x + threadIdx.x;
    int i0 = t * 4;
    if (i0 >= A) { pdl_wait(); return; }

    unsigned long long pol = evict_last_policy();
    const int is64 = g_idx_is64;   // written before dir_kernel's PDL trigger

    if (i0 + 3 < A) {
        int s[4], d[4];
        if (is64) {
            const long long* sp = (const long long*)src_v + i0;
            const long long* dp = (const long long*)dst_v + i0;
            longlong2 sa = ldcs_ll2((const longlong2*)sp);
            longlong2 sb = ldcs_ll2((const longlong2*)(sp + 2));
            longlong2 da = ldcs_ll2((const longlong2*)dp);
            longlong2 db = ldcs_ll2((const longlong2*)(dp + 2));
            s[0] = (int)sa.x; s[1] = (int)sa.y; s[2] = (int)sb.x; s[3] = (int)sb.y;
            d[0] = (int)da.x; d[1] = (int)da.y; d[2] = (int)db.x; d[3] = (int)db.y;
        } else {
            int4 sa = ldcs_i4((const int4*)((const int*)src_v + i0));
            int4 da = ldcs_i4((const int4*)((const int*)dst_v + i0));
            s[0] = sa.x; s[1] = sa.y; s[2] = sa.z; s[3] = sa.w;
            d[0] = da.x; d[1] = da.y; d[2] = da.z; d[3] = da.w;
        }

        // Gate the table gathers on dir_kernel completion.
        pdl_wait();

        // Batch 1: 4 gathers in flight, consume, release registers.
        float4 a0 = ldg_table(&g_dir[s[0]], pol);
        float4 b0 = ldg_table(&g_dir[d[0]], pol);
        float4 a1 = ldg_table(&g_dir[s[1]], pol);
        float4 b1 = ldg_table(&g_dir[d[1]], pol);
        float c0 = a0.x * b0.x + a0.y * b0.y + a0.z * b0.z;
        float c1 = a1.x * b1.x + a1.y * b1.y + a1.z * b1.z;
        float r0 = acosf(0.95f * c0);
        float r1 = acosf(0.95f * c1);

        // Batch 2.
        float4 a2 = ldg_table(&g_dir[s[2]], pol);
        float4 b2 = ldg_table(&g_dir[d[2]], pol);
        float4 a3 = ldg_table(&g_dir[s[3]], pol);
        float4 b3 = ldg_table(&g_dir[d[3]], pol);
        float c2 = a2.x * b2.x + a2.y * b2.y + a2.z * b2.z;
        float c3 = a3.x * b3.x + a3.y * b3.y + a3.z * b3.z;

        float4 r = make_float4(r0, r1, acosf(0.95f * c2), acosf(0.95f * c3));
        stcs_f4((float4*)(out + i0), r);
    } else {
        pdl_wait();
        for (int i = i0; i < A; ++i) {
            int si, di;
            if (is64) {
                si = (int)((const long long*)src_v)[i];
                di = (int)((const long long*)dst_v)[i];
            } else {
                si = ((const int*)src_v)[i];
                di = ((const int*)dst_v)[i];
            }
            float4 a = ldg_table(&g_dir[si], pol);
            float4 b = ldg_table(&g_dir[di], pol);
            float c = a.x * b.x + a.y * b.y + a.z * b.z;
            out[i] = acosf(0.95f * c);
        }
    }
}

// ---------------------------------------------------------------------------
// Launch
// inputs (metadata order): distances [E] f32, vec [E,3] f32,
//                          angle_src [A] i64/i32, angle_dst [A] i64/i32
// output: angles [A] f32
// ---------------------------------------------------------------------------
extern "C" void kernel_launch(void* const* d_in, const int* in_sizes, int n_in,
                              void* d_out, int out_size)
{
    const float* dist = (const float*)d_in[0];
    const float* vec  = (const float*)d_in[1];
    const void*  src  = d_in[2];
    const void*  dst  = d_in[3];
    float*       out  = (float*)d_out;

    int E = in_sizes[0];
    int A = in_sizes[2];
    if (E > MAX_E) E = MAX_E;

    const int T = 256;
    dir_kernel<<<(E + T - 1) / T, T>>>(dist, vec, (const unsigned int*)src, A, E);

    // Angle kernel with programmatic dependent launch: overlaps its index
    // prologue with dir_kernel's tail.
    int threads_needed = (A + 3) / 4;
    int blocks = (threads_needed + T - 1) / T;

    cudaLaunchConfig_t cfg = {};
    cfg.gridDim  = dim3((unsigned)blocks, 1, 1);
    cfg.blockDim = dim3((unsigned)T, 1, 1);
    cfg.dynamicSmemBytes = 0;
    cfg.stream = 0;

    cudaLaunchAttribute attrs[1];
    attrs[0].id = cudaLaunchAttributeProgrammaticStreamSerialization;
    attrs[0].val.programmaticStreamSerializationAllowed = 1;
    cfg.attrs = attrs;
    cfg.numAttrs = 1;

    cudaLaunchKernelEx(&cfg, angle_kernel, (const void*)src, (const void*)dst, out, A);
}